// round 10
// baseline (speedup 1.0000x reference)
#include <cuda_runtime.h>
#include <cuda_fp16.h>

#define N_NODES 50000
#define N_EDGES 800000
#define IN_C    16
#define OUT_C   16
#define EDGE_F  8

// y table in fp16: per node 9 blocks (8 edge-feature + 1 bias) x 16 outputs,
// = 18 uint4, PADDED to 24 uint4 (384 B = 3 cache lines, 128B-aligned).
// slot j = f*2 + h  (f = feature block, h = output half, uint4 units)
#define YSTRIDE 24

#define NGROUP (N_NODES / 4)     // 12500 node-groups of 4 (strided)

__device__ __align__(128) uint4 g_yh[N_NODES * YSTRIDE];   // 19.2 MB
__device__ int g_bias_nz;        // 1 iff any b_nn element nonzero

// ---------------------------------------------------------------------------
// Flag kernel: g_bias_nz = any(b_nn != 0). Unconditional store each launch.
// ---------------------------------------------------------------------------
__global__ void flag_kernel(const float* __restrict__ b_nn)
{
    int v = (b_nn[threadIdx.x] != 0.0f) ? 1 : 0;
    v = __syncthreads_or(v);
    if (threadIdx.x == 0) g_bias_nz = v;
}

// ---------------------------------------------------------------------------
// Kernel A: per-node precompute, 4-node register blocking, 2-way f-split.
// Thread = (node-group, output-half h, part). part0: f=0..3 + root term.
// part1: f=4..8 (incl. bias block). 2x warps vs R9 for latency hiding.
// ---------------------------------------------------------------------------
template<int F0, int F1>
__device__ __forceinline__ void y_blocks(const float* __restrict__ Wsh,
                                         const float xv[4][16],
                                         int grp, int h)
{
    #pragma unroll
    for (int f = F0; f < F1; f++) {
        float acc[4][8];
        #pragma unroll
        for (int k = 0; k < 4; k++)
            #pragma unroll
            for (int o = 0; o < 8; o++) acc[k][o] = 0.f;

        const float* wb = &Wsh[f * 256 + h * 8];
        #pragma unroll
        for (int i = 0; i < 16; i++) {
            const float4 wlo = *(const float4*)(wb + i * 16);
            const float4 whi = *(const float4*)(wb + i * 16 + 4);
            const float w[8] = {wlo.x, wlo.y, wlo.z, wlo.w,
                                whi.x, whi.y, whi.z, whi.w};
            #pragma unroll
            for (int k = 0; k < 4; k++) {
                const float xi = xv[k][i];
                #pragma unroll
                for (int o = 0; o < 8; o++) acc[k][o] += xi * w[o];
            }
        }

        #pragma unroll
        for (int k = 0; k < 4; k++) {
            __half2 hv[4];
            #pragma unroll
            for (int j = 0; j < 4; j++)
                hv[j] = __floats2half2_rn(acc[k][2*j], acc[k][2*j+1]);
            const int n = grp + k * NGROUP;
            g_yh[n * YSTRIDE + f * 2 + h] = *(const uint4*)hv;
        }
    }
}

__global__ void node_kernel(const float* __restrict__ x,
                            const float* __restrict__ w_nn,
                            const float* __restrict__ b_nn,
                            const float* __restrict__ root,
                            const float* __restrict__ bias,
                            float* __restrict__ out)
{
    __shared__ float Wsh[9 * 256];      // [f][i*16+o], f==8 holds b_nn
    __shared__ float Rsh[256 + 16];     // root [i][o] + bias[o]

    for (int t = threadIdx.x; t < 2048; t += blockDim.x) Wsh[t] = w_nn[t];
    for (int t = threadIdx.x; t < 256;  t += blockDim.x) Wsh[2048 + t] = b_nn[t];
    for (int t = threadIdx.x; t < 256;  t += blockDim.x) Rsh[t] = root[t];
    for (int t = threadIdx.x; t < 16;   t += blockDim.x) Rsh[256 + t] = bias[t];
    __syncthreads();

    const int gsz  = gridDim.x * blockDim.x;
    const int tid0 = blockIdx.x * blockDim.x + threadIdx.x;

    for (int t = tid0; t < NGROUP * 4; t += gsz) {     // 50000 tasks
        const int grp  = t >> 2;
        const int h    = (t >> 1) & 1;     // outputs h*8 .. h*8+7
        const int part = t & 1;

        // ---- load x for 4 strided nodes into registers ----
        float xv[4][16];
        #pragma unroll
        for (int k = 0; k < 4; k++) {
            const int n = grp + k * NGROUP;
            const float4* xr = (const float4*)(x + n * IN_C);
            #pragma unroll
            for (int ii = 0; ii < 4; ii++) {
                float4 xx = xr[ii];
                xv[k][4*ii+0] = xx.x; xv[k][4*ii+1] = xx.y;
                xv[k][4*ii+2] = xx.z; xv[k][4*ii+3] = xx.w;
            }
        }

        if (part == 0) {
            y_blocks<0, 4>(Wsh, xv, grp, h);

            // ---- fused root-term halves for the 4 nodes ----
            float racc[4][8];
            #pragma unroll
            for (int k = 0; k < 4; k++)
                #pragma unroll
                for (int o = 0; o < 8; o++) racc[k][o] = Rsh[256 + h * 8 + o];

            #pragma unroll
            for (int i = 0; i < 16; i++) {
                const float4 rlo = *(const float4*)&Rsh[i * 16 + h * 8];
                const float4 rhi = *(const float4*)&Rsh[i * 16 + h * 8 + 4];
                const float r[8] = {rlo.x, rlo.y, rlo.z, rlo.w,
                                    rhi.x, rhi.y, rhi.z, rhi.w};
                #pragma unroll
                for (int k = 0; k < 4; k++) {
                    const float xi = xv[k][i];
                    #pragma unroll
                    for (int o = 0; o < 8; o++) racc[k][o] += xi * r[o];
                }
            }

            #pragma unroll
            for (int k = 0; k < 4; k++) {
                const int n = grp + k * NGROUP;
                float4* od = (float4*)(out + n * OUT_C + h * 8);
                od[0] = make_float4(racc[k][0], racc[k][1], racc[k][2], racc[k][3]);
                od[1] = make_float4(racc[k][4], racc[k][5], racc[k][6], racc[k][7]);
            }
        } else {
            y_blocks<4, 9>(Wsh, xv, grp, h);
        }
    }
}

// ---------------------------------------------------------------------------
// Kernel B: 4 lanes per edge (8 edges/warp), single red.v4 scatter, echo in
// the DRAM shadow. NEW: bias-block gather skipped when b_nn == 0 (exact).
// ---------------------------------------------------------------------------
__global__ void edge_kernel(const int*   __restrict__ ei,
                            const float* __restrict__ ea,
                            float* __restrict__ out,
                            int echo)
{
    const int g   = blockIdx.x * blockDim.x + threadIdx.x;
    const int e   = g >> 2;                 // edge id (grid exact: N_EDGES*4 thr)
    const int sub = g & 3;
    const int s2  = sub >> 1;               // f-parity this lane handles

    const int bias_nz = g_bias_nz;          // uniform, L1-broadcast after 1st ld

    const int src = __ldg(&ei[e]);
    const int dst = __ldg(&ei[N_EDGES + e]);

    // edge coefficients: lane needs f = s2, s2+2, s2+4, s2+6
    const float4* ea4 = (const float4*)ea;
    const float4 a0 = ea4[2 * e];
    const float4 a1 = ea4[2 * e + 1];
    const float c0 = s2 ? a0.y : a0.x;
    const float c1 = s2 ? a0.w : a0.z;
    const float c2 = s2 ? a1.y : a1.x;
    const float c3 = s2 ? a1.w : a1.z;

    const uint4* yrow = g_yh + src * YSTRIDE;
    const uint4 v0 = yrow[sub];
    const uint4 v1 = yrow[sub + 4];
    const uint4 v2 = yrow[sub + 8];
    const uint4 v3 = yrow[sub + 12];

    float acc[8];
    #pragma unroll
    for (int o = 0; o < 8; o++) acc[o] = 0.f;

    #pragma unroll
    for (int b = 0; b < 4; b++) {
        const uint4  v  = (b == 0) ? v0 : (b == 1) ? v1 : (b == 2) ? v2 : v3;
        const float  cf = (b == 0) ? c0 : (b == 1) ? c1 : (b == 2) ? c2 : c3;
        const __half2* hv = (const __half2*)&v;
        #pragma unroll
        for (int j = 0; j < 4; j++) {
            float2 p = __half22float2(hv[j]);
            acc[2*j]   += cf * p.x;
            acc[2*j+1] += cf * p.y;
        }
    }

    // bias block (f=8, coef 1) — only when b_nn is not identically zero
    if (bias_nz && sub < 2) {
        const uint4 vb = yrow[16 + sub];
        const __half2* hv = (const __half2*)&vb;
        #pragma unroll
        for (int j = 0; j < 4; j++) {
            float2 p = __half22float2(hv[j]);
            acc[2*j]   += p.x;
            acc[2*j+1] += p.y;
        }
    }

    // combine the two f-parities: lane pairs (0,2) and (1,3).
    // Afterwards lanes 0,2 both hold outputs 0..7; lanes 1,3 hold 8..15.
    #pragma unroll
    for (int o = 0; o < 8; o++)
        acc[o] += __shfl_xor_sync(0xffffffffu, acc[o], 2);

    // ONE red.v4 instruction covers the whole 64 B dst row:
    //   sub0 -> [0:4)=acc[0:4], sub2 -> [4:8)=acc[4:8],
    //   sub1 -> [8:12)=acc[0:4], sub3 -> [12:16)=acc[4:8]
    {
        float* o = out + dst * OUT_C + (sub & 1) * 8 + s2 * 4;
        float r0, r1, r2, r3;
        if (s2) { r0 = acc[4]; r1 = acc[5]; r2 = acc[6]; r3 = acc[7]; }
        else    { r0 = acc[0]; r1 = acc[1]; r2 = acc[2]; r3 = acc[3]; }
        asm volatile("red.global.add.v4.f32 [%0], {%1, %2, %3, %4};"
                     :: "l"(o), "f"(r0), "f"(r1), "f"(r2), "f"(r3)
                     : "memory");
    }

    // ---- echo streaming, riding the DRAM shadow ----
    if (g < 2 * N_EDGES) {
        if (echo & 1)
            out[N_NODES * OUT_C + g] = (float)__ldg(&ei[g]);
        if (echo & 2) {
            float4*       dst4 = (float4*)(out + N_NODES * OUT_C + 2 * N_EDGES);
            const float4* src4 = (const float4*)ea;
            dst4[g] = src4[g];
        }
    }
}

extern "C" void kernel_launch(void* const* d_in, const int* in_sizes, int n_in,
                              void* d_out, int out_size)
{
    const float* x     = (const float*)d_in[0];
    const int*   ei    = (const int*)  d_in[1];
    const float* ea    = (const float*)d_in[2];
    const float* w_nn  = (const float*)d_in[3];
    const float* b_nn  = (const float*)d_in[4];
    const float* root  = (const float*)d_in[5];
    const float* bias  = (const float*)d_in[6];
    float* out = (float*)d_out;

    int echo = 0;
    if (out_size >= N_NODES * OUT_C + 2 * N_EDGES)                        echo |= 1;
    if (out_size >= N_NODES * OUT_C + 2 * N_EDGES + N_EDGES * EDGE_F)     echo |= 2;

    flag_kernel<<<1, 256>>>(b_nn);
    // 50000 tasks (node-group x half x part); 196 blocks x 256
    node_kernel<<<196, 256>>>(x, w_nn, b_nn, root, bias, out);
    edge_kernel<<<(N_EDGES * 4) / 256, 256>>>(ei, ea, out, echo);
}

// round 13
// speedup vs baseline: 1.0364x; 1.0364x over previous
#include <cuda_runtime.h>
#include <cuda_fp16.h>

#define N_NODES 50000
#define N_EDGES 800000
#define IN_C    16
#define OUT_C   16
#define EDGE_F  8

// y table in fp16: per node 9 blocks (8 edge-feature + 1 bias) x 16 outputs,
// = 18 uint4, PADDED to 24 uint4 (384 B = 3 cache lines, 128B-aligned).
// slot j = f*2 + h  (f = feature block, h = output half, uint4 units)
#define YSTRIDE 24

#define NGROUP (N_NODES / 4)     // 12500 node-groups of 4 (strided)

__device__ __align__(128) uint4 g_yh[N_NODES * YSTRIDE];   // 19.2 MB
__device__ int g_bias_nz;        // 1 iff any b_nn element nonzero

// ---------------------------------------------------------------------------
// Kernel A: per-node precompute, 4-node register blocking, 2-way f-split.
// Thread = (node-group, output-half h, part). part0: f=0..3 + root term.
// part1: f=4..8 (incl. bias block).
// Block 0 additionally reduces b_nn into g_bias_nz (no extra launch; the
// kernel boundary orders the store before edge_kernel's load).
// ---------------------------------------------------------------------------
template<int F0, int F1>
__device__ __forceinline__ void y_blocks(const float* __restrict__ Wsh,
                                         const float xv[4][16],
                                         int grp, int h)
{
    #pragma unroll
    for (int f = F0; f < F1; f++) {
        float acc[4][8];
        #pragma unroll
        for (int k = 0; k < 4; k++)
            #pragma unroll
            for (int o = 0; o < 8; o++) acc[k][o] = 0.f;

        const float* wb = &Wsh[f * 256 + h * 8];
        #pragma unroll
        for (int i = 0; i < 16; i++) {
            const float4 wlo = *(const float4*)(wb + i * 16);
            const float4 whi = *(const float4*)(wb + i * 16 + 4);
            const float w[8] = {wlo.x, wlo.y, wlo.z, wlo.w,
                                whi.x, whi.y, whi.z, whi.w};
            #pragma unroll
            for (int k = 0; k < 4; k++) {
                const float xi = xv[k][i];
                #pragma unroll
                for (int o = 0; o < 8; o++) acc[k][o] += xi * w[o];
            }
        }

        #pragma unroll
        for (int k = 0; k < 4; k++) {
            __half2 hv[4];
            #pragma unroll
            for (int j = 0; j < 4; j++)
                hv[j] = __floats2half2_rn(acc[k][2*j], acc[k][2*j+1]);
            const int n = grp + k * NGROUP;
            g_yh[n * YSTRIDE + f * 2 + h] = *(const uint4*)hv;
        }
    }
}

__global__ void node_kernel(const float* __restrict__ x,
                            const float* __restrict__ w_nn,
                            const float* __restrict__ b_nn,
                            const float* __restrict__ root,
                            const float* __restrict__ bias,
                            float* __restrict__ out)
{
    __shared__ float Wsh[9 * 256];      // [f][i*16+o], f==8 holds b_nn
    __shared__ float Rsh[256 + 16];     // root [i][o] + bias[o]

    for (int t = threadIdx.x; t < 2048; t += blockDim.x) Wsh[t] = w_nn[t];
    for (int t = threadIdx.x; t < 256;  t += blockDim.x) Wsh[2048 + t] = b_nn[t];
    for (int t = threadIdx.x; t < 256;  t += blockDim.x) Rsh[t] = root[t];
    for (int t = threadIdx.x; t < 16;   t += blockDim.x) Rsh[256 + t] = bias[t];
    __syncthreads();

    // ---- inline bias flag (block 0 only, piggybacks on staged smem) ----
    if (blockIdx.x == 0) {
        int v = (threadIdx.x < 256) ? (Wsh[2048 + threadIdx.x] != 0.0f) : 0;
        v = __syncthreads_or(v);
        if (threadIdx.x == 0) g_bias_nz = v;
    }

    const int gsz  = gridDim.x * blockDim.x;
    const int tid0 = blockIdx.x * blockDim.x + threadIdx.x;

    for (int t = tid0; t < NGROUP * 4; t += gsz) {     // 50000 tasks
        const int grp  = t >> 2;
        const int h    = (t >> 1) & 1;     // outputs h*8 .. h*8+7
        const int part = t & 1;

        // ---- load x for 4 strided nodes into registers ----
        float xv[4][16];
        #pragma unroll
        for (int k = 0; k < 4; k++) {
            const int n = grp + k * NGROUP;
            const float4* xr = (const float4*)(x + n * IN_C);
            #pragma unroll
            for (int ii = 0; ii < 4; ii++) {
                float4 xx = xr[ii];
                xv[k][4*ii+0] = xx.x; xv[k][4*ii+1] = xx.y;
                xv[k][4*ii+2] = xx.z; xv[k][4*ii+3] = xx.w;
            }
        }

        if (part == 0) {
            y_blocks<0, 4>(Wsh, xv, grp, h);

            // ---- fused root-term halves for the 4 nodes ----
            float racc[4][8];
            #pragma unroll
            for (int k = 0; k < 4; k++)
                #pragma unroll
                for (int o = 0; o < 8; o++) racc[k][o] = Rsh[256 + h * 8 + o];

            #pragma unroll
            for (int i = 0; i < 16; i++) {
                const float4 rlo = *(const float4*)&Rsh[i * 16 + h * 8];
                const float4 rhi = *(const float4*)&Rsh[i * 16 + h * 8 + 4];
                const float r[8] = {rlo.x, rlo.y, rlo.z, rlo.w,
                                    rhi.x, rhi.y, rhi.z, rhi.w};
                #pragma unroll
                for (int k = 0; k < 4; k++) {
                    const float xi = xv[k][i];
                    #pragma unroll
                    for (int o = 0; o < 8; o++) racc[k][o] += xi * r[o];
                }
            }

            #pragma unroll
            for (int k = 0; k < 4; k++) {
                const int n = grp + k * NGROUP;
                float4* od = (float4*)(out + n * OUT_C + h * 8);
                od[0] = make_float4(racc[k][0], racc[k][1], racc[k][2], racc[k][3]);
                od[1] = make_float4(racc[k][4], racc[k][5], racc[k][6], racc[k][7]);
            }
        } else {
            y_blocks<4, 9>(Wsh, xv, grp, h);
        }
    }
}

// ---------------------------------------------------------------------------
// Kernel B: 4 lanes per edge (8 edges/warp), single red.v4 scatter, echo in
// the DRAM shadow; bias-block gather skipped when b_nn == 0 (exact).
// ---------------------------------------------------------------------------
__global__ void edge_kernel(const int*   __restrict__ ei,
                            const float* __restrict__ ea,
                            float* __restrict__ out,
                            int echo)
{
    const int g   = blockIdx.x * blockDim.x + threadIdx.x;
    const int e   = g >> 2;                 // edge id (grid exact: N_EDGES*4 thr)
    const int sub = g & 3;
    const int s2  = sub >> 1;               // f-parity this lane handles

    const int bias_nz = g_bias_nz;          // uniform, cached after first load

    const int src = __ldg(&ei[e]);
    const int dst = __ldg(&ei[N_EDGES + e]);

    // edge coefficients: lane needs f = s2, s2+2, s2+4, s2+6
    const float4* ea4 = (const float4*)ea;
    const float4 a0 = ea4[2 * e];
    const float4 a1 = ea4[2 * e + 1];
    const float c0 = s2 ? a0.y : a0.x;
    const float c1 = s2 ? a0.w : a0.z;
    const float c2 = s2 ? a1.y : a1.x;
    const float c3 = s2 ? a1.w : a1.z;

    const uint4* yrow = g_yh + src * YSTRIDE;
    const uint4 v0 = yrow[sub];
    const uint4 v1 = yrow[sub + 4];
    const uint4 v2 = yrow[sub + 8];
    const uint4 v3 = yrow[sub + 12];

    float acc[8];
    #pragma unroll
    for (int o = 0; o < 8; o++) acc[o] = 0.f;

    #pragma unroll
    for (int b = 0; b < 4; b++) {
        const uint4  v  = (b == 0) ? v0 : (b == 1) ? v1 : (b == 2) ? v2 : v3;
        const float  cf = (b == 0) ? c0 : (b == 1) ? c1 : (b == 2) ? c2 : c3;
        const __half2* hv = (const __half2*)&v;
        #pragma unroll
        for (int j = 0; j < 4; j++) {
            float2 p = __half22float2(hv[j]);
            acc[2*j]   += cf * p.x;
            acc[2*j+1] += cf * p.y;
        }
    }

    // bias block (f=8, coef 1) — only when b_nn is not identically zero
    if (bias_nz && sub < 2) {
        const uint4 vb = yrow[16 + sub];
        const __half2* hv = (const __half2*)&vb;
        #pragma unroll
        for (int j = 0; j < 4; j++) {
            float2 p = __half22float2(hv[j]);
            acc[2*j]   += p.x;
            acc[2*j+1] += p.y;
        }
    }

    // combine the two f-parities: lane pairs (0,2) and (1,3).
    // Afterwards lanes 0,2 both hold outputs 0..7; lanes 1,3 hold 8..15.
    #pragma unroll
    for (int o = 0; o < 8; o++)
        acc[o] += __shfl_xor_sync(0xffffffffu, acc[o], 2);

    // ONE red.v4 instruction covers the whole 64 B dst row:
    //   sub0 -> [0:4)=acc[0:4], sub2 -> [4:8)=acc[4:8],
    //   sub1 -> [8:12)=acc[0:4], sub3 -> [12:16)=acc[4:8]
    {
        float* o = out + dst * OUT_C + (sub & 1) * 8 + s2 * 4;
        float r0, r1, r2, r3;
        if (s2) { r0 = acc[4]; r1 = acc[5]; r2 = acc[6]; r3 = acc[7]; }
        else    { r0 = acc[0]; r1 = acc[1]; r2 = acc[2]; r3 = acc[3]; }
        asm volatile("red.global.add.v4.f32 [%0], {%1, %2, %3, %4};"
                     :: "l"(o), "f"(r0), "f"(r1), "f"(r2), "f"(r3)
                     : "memory");
    }

    // ---- echo streaming, riding the DRAM shadow ----
    if (g < 2 * N_EDGES) {
        if (echo & 1)
            out[N_NODES * OUT_C + g] = (float)__ldg(&ei[g]);
        if (echo & 2) {
            float4*       dst4 = (float4*)(out + N_NODES * OUT_C + 2 * N_EDGES);
            const float4* src4 = (const float4*)ea;
            dst4[g] = src4[g];
        }
    }
}

extern "C" void kernel_launch(void* const* d_in, const int* in_sizes, int n_in,
                              void* d_out, int out_size)
{
    const float* x     = (const float*)d_in[0];
    const int*   ei    = (const int*)  d_in[1];
    const float* ea    = (const float*)d_in[2];
    const float* w_nn  = (const float*)d_in[3];
    const float* b_nn  = (const float*)d_in[4];
    const float* root  = (const float*)d_in[5];
    const float* bias  = (const float*)d_in[6];
    float* out = (float*)d_out;

    int echo = 0;
    if (out_size >= N_NODES * OUT_C + 2 * N_EDGES)                        echo |= 1;
    if (out_size >= N_NODES * OUT_C + 2 * N_EDGES + N_EDGES * EDGE_F)     echo |= 2;

    // 50000 tasks (node-group x half x part); 196 blocks x 256
    node_kernel<<<196, 256>>>(x, w_nn, b_nn, root, bias, out);
    edge_kernel<<<(N_EDGES * 4) / 256, 256>>>(ei, ea, out, echo);
}

// round 14
// speedup vs baseline: 1.2182x; 1.1754x over previous
#include <cuda_runtime.h>
#include <cuda_fp16.h>

#define N_NODES 50000
#define N_EDGES 800000
#define IN_C    16
#define OUT_C   16
#define EDGE_F  8

// y table in fp16: per node 9 blocks (8 edge-feature + 1 bias) x 16 outputs,
// = 18 uint4, PADDED to 24 uint4 (384 B = 3 cache lines, 128B-aligned).
// slot j = f*2 + h  (f = feature block, h = output half, uint4 units)
#define YSTRIDE 24

#define NPAIR (N_NODES / 2)      // 25000 node-pairs (strided)

__device__ __align__(128) uint4 g_yh[N_NODES * YSTRIDE];   // 19.2 MB
__device__ int g_bias_nz;        // 1 iff any b_nn element nonzero

// ---------------------------------------------------------------------------
// Kernel A: per-node precompute, 2-node register blocking, full task/thread.
// Thread = (node-pair, output-half h): 9 y-blocks + root term for 2 nodes.
// 50000 threads -> ~2.6 warps/SMSP (2x R9's latency hiding) with NO
// duplicated x loads (the R13 split's mistake).
// Block 0 additionally reduces b_nn into g_bias_nz (no extra launch).
// ---------------------------------------------------------------------------
__global__ void node_kernel(const float* __restrict__ x,
                            const float* __restrict__ w_nn,
                            const float* __restrict__ b_nn,
                            const float* __restrict__ root,
                            const float* __restrict__ bias,
                            float* __restrict__ out)
{
    __shared__ float Wsh[9 * 256];      // [f][i*16+o], f==8 holds b_nn
    __shared__ float Rsh[256 + 16];     // root [i][o] + bias[o]

    for (int t = threadIdx.x; t < 2048; t += blockDim.x) Wsh[t] = w_nn[t];
    for (int t = threadIdx.x; t < 256;  t += blockDim.x) Wsh[2048 + t] = b_nn[t];
    for (int t = threadIdx.x; t < 256;  t += blockDim.x) Rsh[t] = root[t];
    for (int t = threadIdx.x; t < 16;   t += blockDim.x) Rsh[256 + t] = bias[t];
    __syncthreads();

    // ---- inline bias flag (block 0 only, piggybacks on staged smem) ----
    if (blockIdx.x == 0) {
        int v = (threadIdx.x < 256) ? (Wsh[2048 + threadIdx.x] != 0.0f) : 0;
        v = __syncthreads_or(v);
        if (threadIdx.x == 0) g_bias_nz = v;
    }

    const int gsz  = gridDim.x * blockDim.x;
    const int tid0 = blockIdx.x * blockDim.x + threadIdx.x;

    for (int t = tid0; t < NPAIR * 2; t += gsz) {      // 50000 tasks
        const int grp = t >> 1;
        const int h   = t & 1;                 // outputs h*8 .. h*8+7

        // ---- load x for 2 strided nodes into registers ----
        float xv[2][16];
        #pragma unroll
        for (int k = 0; k < 2; k++) {
            const int n = grp + k * NPAIR;
            const float4* xr = (const float4*)(x + n * IN_C);
            #pragma unroll
            for (int ii = 0; ii < 4; ii++) {
                float4 xx = xr[ii];
                xv[k][4*ii+0] = xx.x; xv[k][4*ii+1] = xx.y;
                xv[k][4*ii+2] = xx.z; xv[k][4*ii+3] = xx.w;
            }
        }

        // ---- 9 y-blocks: each weight LDS reused for 2 nodes ----
        #pragma unroll
        for (int f = 0; f < 9; f++) {
            float acc[2][8];
            #pragma unroll
            for (int k = 0; k < 2; k++)
                #pragma unroll
                for (int o = 0; o < 8; o++) acc[k][o] = 0.f;

            const float* wb = &Wsh[f * 256 + h * 8];
            #pragma unroll
            for (int i = 0; i < 16; i++) {
                const float4 wlo = *(const float4*)(wb + i * 16);
                const float4 whi = *(const float4*)(wb + i * 16 + 4);
                const float w[8] = {wlo.x, wlo.y, wlo.z, wlo.w,
                                    whi.x, whi.y, whi.z, whi.w};
                #pragma unroll
                for (int k = 0; k < 2; k++) {
                    const float xi = xv[k][i];
                    #pragma unroll
                    for (int o = 0; o < 8; o++) acc[k][o] += xi * w[o];
                }
            }

            #pragma unroll
            for (int k = 0; k < 2; k++) {
                __half2 hv[4];
                #pragma unroll
                for (int j = 0; j < 4; j++)
                    hv[j] = __floats2half2_rn(acc[k][2*j], acc[k][2*j+1]);
                const int n = grp + k * NPAIR;
                g_yh[n * YSTRIDE + f * 2 + h] = *(const uint4*)hv;
            }
        }

        // ---- fused root-term halves for the 2 nodes ----
        {
            float racc[2][8];
            #pragma unroll
            for (int k = 0; k < 2; k++)
                #pragma unroll
                for (int o = 0; o < 8; o++) racc[k][o] = Rsh[256 + h * 8 + o];

            #pragma unroll
            for (int i = 0; i < 16; i++) {
                const float4 rlo = *(const float4*)&Rsh[i * 16 + h * 8];
                const float4 rhi = *(const float4*)&Rsh[i * 16 + h * 8 + 4];
                const float r[8] = {rlo.x, rlo.y, rlo.z, rlo.w,
                                    rhi.x, rhi.y, rhi.z, rhi.w};
                #pragma unroll
                for (int k = 0; k < 2; k++) {
                    const float xi = xv[k][i];
                    #pragma unroll
                    for (int o = 0; o < 8; o++) racc[k][o] += xi * r[o];
                }
            }

            #pragma unroll
            for (int k = 0; k < 2; k++) {
                const int n = grp + k * NPAIR;
                float4* od = (float4*)(out + n * OUT_C + h * 8);
                od[0] = make_float4(racc[k][0], racc[k][1], racc[k][2], racc[k][3]);
                od[1] = make_float4(racc[k][4], racc[k][5], racc[k][6], racc[k][7]);
            }
        }
    }
}

// ---------------------------------------------------------------------------
// Kernel B (unchanged R13 winner): 4 lanes per edge, single red.v4 scatter,
// echo in the DRAM shadow, bias-block gather skipped when b_nn == 0 (exact).
// ---------------------------------------------------------------------------
__global__ void edge_kernel(const int*   __restrict__ ei,
                            const float* __restrict__ ea,
                            float* __restrict__ out,
                            int echo)
{
    const int g   = blockIdx.x * blockDim.x + threadIdx.x;
    const int e   = g >> 2;                 // edge id (grid exact: N_EDGES*4 thr)
    const int sub = g & 3;
    const int s2  = sub >> 1;               // f-parity this lane handles

    const int bias_nz = g_bias_nz;          // uniform, cached after first load

    const int src = __ldg(&ei[e]);
    const int dst = __ldg(&ei[N_EDGES + e]);

    // edge coefficients: lane needs f = s2, s2+2, s2+4, s2+6
    const float4* ea4 = (const float4*)ea;
    const float4 a0 = ea4[2 * e];
    const float4 a1 = ea4[2 * e + 1];
    const float c0 = s2 ? a0.y : a0.x;
    const float c1 = s2 ? a0.w : a0.z;
    const float c2 = s2 ? a1.y : a1.x;
    const float c3 = s2 ? a1.w : a1.z;

    const uint4* yrow = g_yh + src * YSTRIDE;
    const uint4 v0 = yrow[sub];
    const uint4 v1 = yrow[sub + 4];
    const uint4 v2 = yrow[sub + 8];
    const uint4 v3 = yrow[sub + 12];

    float acc[8];
    #pragma unroll
    for (int o = 0; o < 8; o++) acc[o] = 0.f;

    #pragma unroll
    for (int b = 0; b < 4; b++) {
        const uint4  v  = (b == 0) ? v0 : (b == 1) ? v1 : (b == 2) ? v2 : v3;
        const float  cf = (b == 0) ? c0 : (b == 1) ? c1 : (b == 2) ? c2 : c3;
        const __half2* hv = (const __half2*)&v;
        #pragma unroll
        for (int j = 0; j < 4; j++) {
            float2 p = __half22float2(hv[j]);
            acc[2*j]   += cf * p.x;
            acc[2*j+1] += cf * p.y;
        }
    }

    // bias block (f=8, coef 1) — only when b_nn is not identically zero
    if (bias_nz && sub < 2) {
        const uint4 vb = yrow[16 + sub];
        const __half2* hv = (const __half2*)&vb;
        #pragma unroll
        for (int j = 0; j < 4; j++) {
            float2 p = __half22float2(hv[j]);
            acc[2*j]   += p.x;
            acc[2*j+1] += p.y;
        }
    }

    // combine the two f-parities: lane pairs (0,2) and (1,3).
    #pragma unroll
    for (int o = 0; o < 8; o++)
        acc[o] += __shfl_xor_sync(0xffffffffu, acc[o], 2);

    // ONE red.v4 instruction covers the whole 64 B dst row
    {
        float* o = out + dst * OUT_C + (sub & 1) * 8 + s2 * 4;
        float r0, r1, r2, r3;
        if (s2) { r0 = acc[4]; r1 = acc[5]; r2 = acc[6]; r3 = acc[7]; }
        else    { r0 = acc[0]; r1 = acc[1]; r2 = acc[2]; r3 = acc[3]; }
        asm volatile("red.global.add.v4.f32 [%0], {%1, %2, %3, %4};"
                     :: "l"(o), "f"(r0), "f"(r1), "f"(r2), "f"(r3)
                     : "memory");
    }

    // ---- echo streaming, riding the DRAM shadow ----
    if (g < 2 * N_EDGES) {
        if (echo & 1)
            out[N_NODES * OUT_C + g] = (float)__ldg(&ei[g]);
        if (echo & 2) {
            float4*       dst4 = (float4*)(out + N_NODES * OUT_C + 2 * N_EDGES);
            const float4* src4 = (const float4*)ea;
            dst4[g] = src4[g];
        }
    }
}

extern "C" void kernel_launch(void* const* d_in, const int* in_sizes, int n_in,
                              void* d_out, int out_size)
{
    const float* x     = (const float*)d_in[0];
    const int*   ei    = (const int*)  d_in[1];
    const float* ea    = (const float*)d_in[2];
    const float* w_nn  = (const float*)d_in[3];
    const float* b_nn  = (const float*)d_in[4];
    const float* root  = (const float*)d_in[5];
    const float* bias  = (const float*)d_in[6];
    float* out = (float*)d_out;

    int echo = 0;
    if (out_size >= N_NODES * OUT_C + 2 * N_EDGES)                        echo |= 1;
    if (out_size >= N_NODES * OUT_C + 2 * N_EDGES + N_EDGES * EDGE_F)     echo |= 2;

    // 50000 tasks (node-pair x half); 196 blocks x 256
    node_kernel<<<196, 256>>>(x, w_nn, b_nn, root, bias, out);
    edge_kernel<<<(N_EDGES * 4) / 256, 256>>>(ei, ea, out, echo);
}